// round 14
// baseline (speedup 1.0000x reference)
#include <cuda_runtime.h>
#include <math.h>

#define SS        7
#define NPROP     32
#define NCH       128
#define CPB       2               // channels per block
#define NZG       4               // z-groups: bz {0,1},{2,3},{4,5},{6}
#define FD        32
#define FH        64
#define FW        64
#define CHVOL     (FD * FH * FW)
#define LMAX      18              // max crop extent per dim
#define NZMAX     8               // max z-slices per z-group (2*18/7+2)
#define THREADS   256
#define RSTRIDE   36              // floor(256/7) row-slots in phase 1

__global__ __launch_bounds__(THREADS, 8)
void crop_roi_kernel(const float* __restrict__ f,
                     const float* __restrict__ proposals,
                     float* __restrict__ out)
{
    __shared__ float crop7[CPB][NZMAX * LMAX * SS];     // 8064 B  x-pooled slices

    const int n   = blockIdx.x;
    const int cg  = blockIdx.y;                         // c = cg*CPB + {0,1}
    const int zg  = blockIdx.z;                         // z-group
    const int tid = threadIdx.x;

    // ---- Geometry (registers only) ----
    const float* p = proposals + n * 8;
    const int b = (int)p[0];

    int c0[3], L[3];
    const int dims[3] = {FD, FH, FW};
#pragma unroll
    for (int d = 0; d < 3; d++) {
        const float ctr = p[2 + d];
        const float sd  = p[5 + d];
        int lo = (int)floorf((ctr - 0.5f * sd) * 0.25f);
        int hi = (int)ceilf ((ctr + 0.5f * sd) * 0.25f);
        lo = max(lo, 0);
        hi = min(hi, dims[d]);
        c0[d] = lo;
        L[d]  = hi - lo;     // >= 4 (side >= 16)
    }
    const int Lz = L[0], Ly = L[1], Lx = L[2];

    // This block's bz range and z-slice coverage
    const int bz_lo = zg * 2;
    const int nbz   = (zg < 3) ? 2 : 1;
    const int z0g   =  bz_lo * Lz / SS;                          // first slice
    const int z1g   = ((bz_lo + nbz) * Lz + SS - 1) / SS;        // one past last
    const int nz    = z1g - z0g;                                 // <= 8
    const int nrows = nz * Ly;                                   // <= 144

    // ---- Phase 1: x-pool gmem -> crop7[ch][r*7 + bx] (local slices) ----
    // Thread layout: tid = r0*7 + bx (x-window constant per thread).
    {
        const int bx = tid % SS;
        const int r0 = tid / SS;                        // 0..36
        const int x0 =  bx      * Lx / SS;
        const int x1 = ((bx + 1) * Lx + SS - 1) / SS;
        const int w  = x1 - x0;                         // 1..4, per-thread constant

        if (r0 < RSTRIDE) {
            int zloc = r0 / Ly;                         // one div, once
            int y    = r0 - zloc * Ly;
            int off  = (zloc * FH + y) * FW;            // relative to (z0g, c0y, 0)

            const float* fbase = f
                + ((size_t)b * NCH + cg * CPB) * (size_t)CHVOL
                + ((c0[0] + z0g) * FH + c0[1]) * FW + c0[2] + x0;
            const int ZFIX = (FH - Ly) * FW;
            const int STEP = RSTRIDE * FW;

            for (int r = r0; r < nrows; r += RSTRIDE) {
                const float* rp0 = fbase + off;
                const float* rp1 = rp0 + CHVOL;
                // 8 independent loads in flight per iteration
                float m0 = __ldg(rp0);
                float m1 = __ldg(rp1);
                if (w > 1) { m0 = fmaxf(m0, __ldg(rp0 + 1)); m1 = fmaxf(m1, __ldg(rp1 + 1)); }
                if (w > 2) { m0 = fmaxf(m0, __ldg(rp0 + 2)); m1 = fmaxf(m1, __ldg(rp1 + 2)); }
                if (w > 3) { m0 = fmaxf(m0, __ldg(rp0 + 3)); m1 = fmaxf(m1, __ldg(rp1 + 3)); }
                crop7[0][r * SS + bx] = m0;
                crop7[1][r * SS + bx] = m1;

                off += STEP;
                y   += RSTRIDE;
                while (y >= Ly) { y -= Ly; off += ZFIX; }
            }
        }
    }
    __syncthreads();

    // ---- Phase 2 (fused y+z pool): crop7 -> out, single pass ----
    // Thread layout: tid = s0*49 + rem; s0 encodes (ch, bz-in-group).
    float* outp = out + ((size_t)n * NCH + cg * CPB) * (SS * SS * SS);
    {
        const int rem = tid % (SS * SS);                // by*7+bx
        const int s0  = tid / (SS * SS);                // 0..5; valid: < 2*nbz
        const int by  = rem / SS;
        const int bx  = rem - by * SS;
        const int y0  =  by      * Ly / SS;
        const int y1  = ((by + 1) * Ly + SS - 1) / SS;
        const int wy  = y1 - y0;                        // 1..4

        const int ch  = s0 & 1;
        const int bzi = s0 >> 1;                        // 0..2
        if (bzi < nbz) {
            const int bz  = bz_lo + bzi;
            const int zb0 =  bz      * Lz / SS - z0g;   // local slice range
            const int zb1 = ((bz + 1) * Lz + SS - 1) / SS - z0g;

            float m = -INFINITY;
            for (int zz = zb0; zz < zb1; zz++) {
                const float* rp = &crop7[ch][(zz * Ly + y0) * SS + bx];
                float my = rp[0];
                if (wy > 1) my = fmaxf(my, rp[SS]);
                if (wy > 2) my = fmaxf(my, rp[2 * SS]);
                if (wy > 3) my = fmaxf(my, rp[3 * SS]);
                m = fmaxf(m, my);
            }
            outp[ch * (SS * SS * SS) + bz * (SS * SS) + rem] = m;
        }
    }
}

extern "C" void kernel_launch(void* const* d_in, const int* in_sizes, int n_in,
                              void* d_out, int out_size)
{
    const float* f         = (const float*)d_in[0];
    const float* proposals = (const float*)d_in[2];
    float* out = (float*)d_out;

    dim3 grid(NPROP, NCH / CPB, NZG);
    crop_roi_kernel<<<grid, THREADS>>>(f, proposals, out);
}

// round 16
// speedup vs baseline: 1.2092x; 1.2092x over previous
#include <cuda_runtime.h>
#include <math.h>

#define SS        7
#define NPROP     32
#define NCH       128
#define CPB       2               // channels per thread
#define NCG       (NCH / CPB)     // 64 channel groups
#define FD        32
#define FH        64
#define FW        64
#define CHVOL     (FD * FH * FW)
#define BINS      (SS * SS * SS)  // 343
#define TOTAL     (NPROP * NCG * BINS)   // 702464
#define THREADS   256
#define NEG_INF   (-__int_as_float(0x7f800000))

__global__ __launch_bounds__(THREADS, 8)
void crop_roi_kernel(const float* __restrict__ f,
                     const float* __restrict__ proposals,
                     float* __restrict__ out)
{
    const int gid = blockIdx.x * THREADS + threadIdx.x;
    if (gid >= TOTAL) return;

    // Decode gid -> (n, cg, bin); all divisors compile-time constants.
    const int n    = gid / (NCG * BINS);
    const int r1   = gid - n * (NCG * BINS);
    const int cg   = r1 / BINS;
    const int bin  = r1 - cg * BINS;
    const int bz   = bin / (SS * SS);
    const int r2   = bin - bz * (SS * SS);
    const int by   = r2 / SS;
    const int bx   = r2 - by * SS;

    // ---- Geometry ----
    const float* p = proposals + n * 8;
    const int b = (int)p[0];

    int c0[3], L[3];
    const int dims[3] = {FD, FH, FW};
#pragma unroll
    for (int d = 0; d < 3; d++) {
        const float ctr = p[2 + d];
        const float sd  = p[5 + d];
        int lo = (int)floorf((ctr - 0.5f * sd) * 0.25f);
        int hi = (int)ceilf ((ctr + 0.5f * sd) * 0.25f);
        lo = max(lo, 0);
        hi = min(hi, dims[d]);
        c0[d] = lo;
        L[d]  = hi - lo;     // >= 4 (side >= 16)
    }
    const int Lz = L[0], Ly = L[1], Lx = L[2];

    // ---- Per-bin windows (each 1..4 wide) ----
    const int z0 =  bz      * Lz / SS;
    const int z1 = ((bz + 1) * Lz + SS - 1) / SS;
    const int y0 =  by      * Ly / SS;
    const int y1 = ((by + 1) * Ly + SS - 1) / SS;
    const int x0 =  bx      * Lx / SS;
    const int x1 = ((bx + 1) * Lx + SS - 1) / SS;
    const int w  = x1 - x0;                             // 1..4

    // Base pointer at (c0z+z0, c0y+y0, c0x+x0) of channel cg*CPB
    const float* base0 = f
        + ((size_t)b * NCH + cg * CPB) * (size_t)CHVOL
        + ((c0[0] + z0) * FH + (c0[1] + y0)) * FW + c0[2] + x0;

    float m0 = NEG_INF, m1 = NEG_INF;
    const float* zp = base0;
    for (int zz = z0; zz < z1; zz++) {
        const float* yp = zp;
        for (int yy = y0; yy < y1; yy++) {
            const float* rp0 = yp;
            const float* rp1 = yp + CHVOL;
            // 8 independent loads in flight (2 channels x up-to-4 window)
            float a0 = __ldg(rp0);
            float b0v = __ldg(rp1);
            if (w > 1) { a0 = fmaxf(a0, __ldg(rp0 + 1)); b0v = fmaxf(b0v, __ldg(rp1 + 1)); }
            if (w > 2) { a0 = fmaxf(a0, __ldg(rp0 + 2)); b0v = fmaxf(b0v, __ldg(rp1 + 2)); }
            if (w > 3) { a0 = fmaxf(a0, __ldg(rp0 + 3)); b0v = fmaxf(b0v, __ldg(rp1 + 3)); }
            m0 = fmaxf(m0, a0);
            m1 = fmaxf(m1, b0v);
            yp += FW;
        }
        zp += FH * FW;
    }

    // Output: out[(n*NCH + cg*CPB + ch)*343 + bin]; consecutive lanes -> consecutive bins.
    float* outp = out + ((size_t)n * NCH + cg * CPB) * BINS + bin;
    outp[0]    = m0;
    outp[BINS] = m1;
}

extern "C" void kernel_launch(void* const* d_in, const int* in_sizes, int n_in,
                              void* d_out, int out_size)
{
    const float* f         = (const float*)d_in[0];
    const float* proposals = (const float*)d_in[2];
    float* out = (float*)d_out;

    const int nblocks = (TOTAL + THREADS - 1) / THREADS;   // 2744
    crop_roi_kernel<<<nblocks, THREADS>>>(f, proposals, out);
}

// round 17
// speedup vs baseline: 1.3200x; 1.0917x over previous
#include <cuda_runtime.h>
#include <math.h>

#define SS        7
#define NPROP     32
#define NCH       128
#define CPB       2               // channels per block
#define FD        32
#define FH        64
#define FW        64
#define CHVOL     (FD * FH * FW)
#define LMAX      18              // max crop extent per dim
#define NROWMAX   (LMAX * LMAX)   // 324
#define THREADS   256
#define RSTRIDE   36              // floor(256/7) row-slots in phase 1
#define NSLOT     5               // floor(256/49) slots in fused pool phase
#define NEG_INF   (-__int_as_float(0x7f800000))

__global__ __launch_bounds__(THREADS, 6)
void crop_roi_kernel(const float* __restrict__ f,
                     const float* __restrict__ proposals,
                     float* __restrict__ out)
{
    __shared__ float crop7[CPB][NROWMAX * SS];          // 18144 B  x-pooled

    const int n   = blockIdx.x;
    const int cg  = blockIdx.y;                         // c = cg*CPB + {0,1}
    const int tid = threadIdx.x;

    // ---- Geometry (registers only) ----
    const float* p = proposals + n * 8;
    const int b = (int)p[0];

    int c0[3], L[3];
    const int dims[3] = {FD, FH, FW};
#pragma unroll
    for (int d = 0; d < 3; d++) {
        const float ctr = p[2 + d];
        const float sd  = p[5 + d];
        int lo = (int)floorf((ctr - 0.5f * sd) * 0.25f);
        int hi = (int)ceilf ((ctr + 0.5f * sd) * 0.25f);
        lo = max(lo, 0);
        hi = min(hi, dims[d]);
        c0[d] = lo;
        L[d]  = hi - lo;     // >= 4 (side >= 16)
    }
    const int Lz = L[0], Ly = L[1], Lx = L[2];
    const int nrows = Lz * Ly;                          // <= 324

    // ---- Phase 1: x-pool gmem -> crop7[ch][r*7 + bx], vectorized loads ----
    // Thread layout: tid = r0*7 + bx. Window [x0, x0+w) loaded via 1-2 aligned
    // float4s; out-of-window lanes masked to -INF by adding precomputed masks.
    {
        const int bx = tid % SS;
        const int r0 = tid / SS;                        // 0..36
        const int x0 =  bx      * Lx / SS;
        const int x1 = ((bx + 1) * Lx + SS - 1) / SS;
        const int w  = x1 - x0;                         // 1..4, per-thread constant

        if (r0 < RSTRIDE) {
            const int X0 = c0[2] + x0;                  // global x of window start
            const int q0 = X0 >> 2;                     // aligned quad index
            const int s  = X0 & 3;                      // start within quad
            const int e  = s + w;                       // end within 8-elem span
            const bool straddle = (e > 4);

            // Per-thread constant masks: 0 if element j in [s, e), else -INF.
            float k0 = (0 >= s && 0 < e) ? 0.0f : NEG_INF;
            float k1 = (1 >= s && 1 < e) ? 0.0f : NEG_INF;
            float k2 = (2 >= s && 2 < e) ? 0.0f : NEG_INF;
            float k3 = (3 >= s && 3 < e) ? 0.0f : NEG_INF;
            float k4 = (4 <  e)          ? 0.0f : NEG_INF;   // j=4: j>=s always
            float k5 = (5 <  e)          ? 0.0f : NEG_INF;
            float k6 = (6 <  e)          ? 0.0f : NEG_INF;
            float k7 = (7 <  e)          ? 0.0f : NEG_INF;

            int z = r0 / Ly;
            int y = r0 - z * Ly;
            int off = (z * FH + y) * FW;

            const float* fqbase = f
                + ((size_t)b * NCH + cg * CPB) * (size_t)CHVOL
                + (c0[0] * FH + c0[1]) * FW + q0 * 4;   // 16B-aligned + row-aligned
            const int ZFIX = (FH - Ly) * FW;
            const int STEP = RSTRIDE * FW;

            for (int r = r0; r < nrows; r += RSTRIDE) {
                const float4* rp0 = (const float4*)(fqbase + off);
                const float4* rp1 = (const float4*)(fqbase + off + CHVOL);
                const float4 A0 = __ldg(rp0);
                const float4 A1 = __ldg(rp1);
                float m0 = fmaxf(fmaxf(A0.x + k0, A0.y + k1), fmaxf(A0.z + k2, A0.w + k3));
                float m1 = fmaxf(fmaxf(A1.x + k0, A1.y + k1), fmaxf(A1.z + k2, A1.w + k3));
                if (straddle) {
                    const float4 B0 = __ldg(rp0 + 1);
                    const float4 B1 = __ldg(rp1 + 1);
                    m0 = fmaxf(m0, fmaxf(fmaxf(B0.x + k4, B0.y + k5), fmaxf(B0.z + k6, B0.w + k7)));
                    m1 = fmaxf(m1, fmaxf(fmaxf(B1.x + k4, B1.y + k5), fmaxf(B1.z + k6, B1.w + k7)));
                }
                crop7[0][r * SS + bx] = m0;
                crop7[1][r * SS + bx] = m1;

                off += STEP;
                y   += RSTRIDE;
                while (y >= Ly) { y -= Ly; off += ZFIX; }
            }
        }
    }
    __syncthreads();

    // ---- Phase 2 (fused y+z pool): crop7 -> out directly ----
    float* outp = out + ((size_t)n * NCH + cg * CPB) * (SS * SS * SS);
    {
        const int rem = tid % (SS * SS);                // by*7+bx, constant
        const int s0  = tid / (SS * SS);                // 0..5
        const int by  = rem / SS;
        const int bx  = rem - by * SS;
        const int y0  =  by      * Ly / SS;
        const int y1  = ((by + 1) * Ly + SS - 1) / SS;
        const int wy  = y1 - y0;                        // 1..4, constant

        if (s0 < NSLOT) {
            // 14 tasks: s = ch*7 + bz
            for (int s = s0; s < CPB * SS; s += NSLOT) {
                const int ch = (s < SS) ? 0 : 1;
                const int bz = (s < SS) ? s : s - SS;
                const int z0 =  bz      * Lz / SS;
                const int z1 = ((bz + 1) * Lz + SS - 1) / SS;

                float m = NEG_INF;
                for (int zz = z0; zz < z1; zz++) {
                    const float* rp = &crop7[ch][(zz * Ly + y0) * SS + bx];
                    float my = rp[0];
                    if (wy > 1) my = fmaxf(my, rp[SS]);
                    if (wy > 2) my = fmaxf(my, rp[2 * SS]);
                    if (wy > 3) my = fmaxf(my, rp[3 * SS]);
                    m = fmaxf(m, my);
                }
                outp[ch * (SS * SS * SS) + bz * (SS * SS) + rem] = m;
            }
        }
    }
}

extern "C" void kernel_launch(void* const* d_in, const int* in_sizes, int n_in,
                              void* d_out, int out_size)
{
    const float* f         = (const float*)d_in[0];
    const float* proposals = (const float*)d_in[2];
    float* out = (float*)d_out;

    dim3 grid(NPROP, NCH / CPB);
    crop_roi_kernel<<<grid, THREADS>>>(f, proposals, out);
}